// round 1
// baseline (speedup 1.0000x reference)
#include <cuda_runtime.h>
#include <math.h>

// Problem constants
#define B 32
#define L 4096
#define H 1024
#define GCHUNKS 32           // g-dimension split for deterministic partial sums

// Scratch (device globals — no allocation allowed)
__device__ float g_vpart[GCHUNKS][B * H];   // 4 MB partial sums for v = hid @ W
__device__ float g_v[B * H];                // 128 KB
__device__ float g_energies[B * L];         // 512 KB

// ---------------------------------------------------------------------------
// Kernel 1: partial v[b,h] = sum_{g in chunk} hid[b,g] * W[g,h]
// grid = (H/256, GCHUNKS), block = 256. Each thread owns one h for all 32 b.
// ---------------------------------------------------------------------------
__global__ void k_vpart(const float* __restrict__ hid, const float* __restrict__ W)
{
    __shared__ float sh[B][32];  // hid tile [b][gi], 4 KB; gi range = 32
    const int h  = blockIdx.x * 256 + threadIdx.x;
    const int g0 = blockIdx.y * 32;

    // cooperative load of the hid tile (1024 elems, 256 threads)
    for (int i = threadIdx.x; i < B * 32; i += 256) {
        int b = i >> 5, gi = i & 31;
        sh[b][gi] = hid[b * H + g0 + gi];
    }
    __syncthreads();

    float acc[B];
#pragma unroll
    for (int b = 0; b < B; b++) acc[b] = 0.f;

#pragma unroll
    for (int gi = 0; gi < 32; gi += 4) {
        const float w0 = W[(size_t)(g0 + gi + 0) * H + h];
        const float w1 = W[(size_t)(g0 + gi + 1) * H + h];
        const float w2 = W[(size_t)(g0 + gi + 2) * H + h];
        const float w3 = W[(size_t)(g0 + gi + 3) * H + h];
#pragma unroll
        for (int b = 0; b < B; b++) {
            float4 hv = *reinterpret_cast<const float4*>(&sh[b][gi]); // broadcast LDS.128
            acc[b] = fmaf(hv.x, w0, acc[b]);
            acc[b] = fmaf(hv.y, w1, acc[b]);
            acc[b] = fmaf(hv.z, w2, acc[b]);
            acc[b] = fmaf(hv.w, w3, acc[b]);
        }
    }
#pragma unroll
    for (int b = 0; b < B; b++)
        g_vpart[blockIdx.y][b * H + h] = acc[b];
}

// ---------------------------------------------------------------------------
// Kernel 2: deterministic reduce of partials: v[i] = sum_gc vpart[gc][i]
// ---------------------------------------------------------------------------
__global__ void k_vreduce()
{
    const int i = blockIdx.x * blockDim.x + threadIdx.x;  // 0 .. B*H-1
    float s = 0.f;
#pragma unroll
    for (int gc = 0; gc < GCHUNKS; gc++) s += g_vpart[gc][i];
    g_v[i] = s;
}

// ---------------------------------------------------------------------------
// Kernel 3 (the heavy one, HBM-bound): energies[b,l] = v[b] . enc[l,b]
// One warp per (l,b) pair. enc row is 4 KB contiguous -> perfectly coalesced
// LDG.128 x8 per lane (MLP=8). v rows are hot in L1/L2 (128 KB total).
// ---------------------------------------------------------------------------
__global__ void k_energies(const float* __restrict__ enc)
{
    const int lin  = (blockIdx.x * blockDim.x + threadIdx.x) >> 5; // = l*B + b
    const int lane = threadIdx.x & 31;
    if (lin >= B * L) return;

    const int b = lin & (B - 1);
    const int l = lin >> 5;

    const float4* e4 = reinterpret_cast<const float4*>(enc + (size_t)lin * H);
    const float4* v4 = reinterpret_cast<const float4*>(g_v + (size_t)b * H);

    float acc = 0.f;
#pragma unroll
    for (int i = 0; i < 8; i++) {
        float4 a = e4[lane + 32 * i];
        float4 w = v4[lane + 32 * i];
        acc = fmaf(a.x, w.x, acc);
        acc = fmaf(a.y, w.y, acc);
        acc = fmaf(a.z, w.z, acc);
        acc = fmaf(a.w, w.w, acc);
    }
#pragma unroll
    for (int off = 16; off; off >>= 1)
        acc += __shfl_xor_sync(0xFFFFFFFFu, acc, off);

    if (lane == 0) g_energies[(size_t)b * L + l] = acc;
}

// ---------------------------------------------------------------------------
// Kernel 4: row softmax over L, one block per b. out[b,0,l].
// (hid.bias term is constant over l -> cancels in softmax -> omitted.)
// ---------------------------------------------------------------------------
__global__ void k_softmax(float* __restrict__ out)
{
    const int b   = blockIdx.x;
    const int tid = threadIdx.x;            // blockDim = 512
    const float* e = &g_energies[(size_t)b * L];

    float vals[8];
    float m = -INFINITY;
#pragma unroll
    for (int i = 0; i < 8; i++) {
        vals[i] = e[tid + i * 512];
        m = fmaxf(m, vals[i]);
    }

    __shared__ float red[16];
    // block max
#pragma unroll
    for (int off = 16; off; off >>= 1)
        m = fmaxf(m, __shfl_xor_sync(0xFFFFFFFFu, m, off));
    if ((tid & 31) == 0) red[tid >> 5] = m;
    __syncthreads();
    if (tid < 32) {
        float t = (tid < 16) ? red[tid] : -INFINITY;
#pragma unroll
        for (int off = 8; off; off >>= 1)
            t = fmaxf(t, __shfl_xor_sync(0xFFFFFFFFu, t, off));
        if (tid == 0) red[0] = t;
    }
    __syncthreads();
    m = red[0];
    __syncthreads();

    float s = 0.f;
#pragma unroll
    for (int i = 0; i < 8; i++) {
        vals[i] = __expf(vals[i] - m);
        s += vals[i];
    }
    // block sum
#pragma unroll
    for (int off = 16; off; off >>= 1)
        s += __shfl_xor_sync(0xFFFFFFFFu, s, off);
    if ((tid & 31) == 0) red[tid >> 5] = s;
    __syncthreads();
    if (tid < 32) {
        float t = (tid < 16) ? red[tid] : 0.f;
#pragma unroll
        for (int off = 8; off; off >>= 1)
            t += __shfl_xor_sync(0xFFFFFFFFu, t, off);
        if (tid == 0) red[0] = t;
    }
    __syncthreads();
    const float inv = 1.f / red[0];

#pragma unroll
    for (int i = 0; i < 8; i++)
        out[(size_t)b * L + tid + i * 512] = vals[i] * inv;
}

// ---------------------------------------------------------------------------
// Launch: inputs (metadata order): hidden [1,B,H], encoder_outputs [L,B,H],
// W [H,H], b [H]. Output: [B,1,L] float32.
// ---------------------------------------------------------------------------
extern "C" void kernel_launch(void* const* d_in, const int* in_sizes, int n_in,
                              void* d_out, int out_size)
{
    const float* hid = (const float*)d_in[0];
    const float* enc = (const float*)d_in[1];
    const float* W   = (const float*)d_in[2];
    // d_in[3] (bias) is constant over l -> cancels in softmax -> unused.
    float* out = (float*)d_out;

    // 1) v partials: grid (H/256, GCHUNKS)
    k_vpart<<<dim3(H / 256, GCHUNKS), 256>>>(hid, W);
    // 2) deterministic reduce
    k_vreduce<<<(B * H) / 256, 256>>>();
    // 3) energies: one warp per (l,b): B*L warps, 8 warps/block
    k_energies<<<(B * L) / 8, 256>>>(enc);
    // 4) softmax + write output
    k_softmax<<<B, 512>>>(out);
}

// round 2
// speedup vs baseline: 1.0214x; 1.0214x over previous
#include <cuda_runtime.h>
#include <math.h>

// Problem constants
#define B 32
#define L 4096
#define H 1024
#define GCHUNKS 32           // g-dimension split for deterministic partial sums

// Scratch (device globals — no allocation allowed)
__device__ float g_vpart[GCHUNKS][B * H];   // 4 MB partial sums for v = hid @ W
__device__ float g_v[B * H];                // 128 KB
__device__ float g_energies[B * L];         // 512 KB

// ---------------------------------------------------------------------------
// Kernel 1: partial v[b,h] = sum_{g in chunk} hid[b,g] * W[g,h]
// grid = (H/256, GCHUNKS), block = 256. Each thread owns one h for all 32 b.
// ---------------------------------------------------------------------------
__global__ void k_vpart(const float* __restrict__ hid, const float* __restrict__ W)
{
    __shared__ float sh[B][32];  // hid tile [b][gi], 4 KB
    const int h  = blockIdx.x * 256 + threadIdx.x;
    const int g0 = blockIdx.y * 32;

    for (int i = threadIdx.x; i < B * 32; i += 256) {
        int b = i >> 5, gi = i & 31;
        sh[b][gi] = hid[b * H + g0 + gi];
    }
    __syncthreads();

    float acc[B];
#pragma unroll
    for (int b = 0; b < B; b++) acc[b] = 0.f;

#pragma unroll
    for (int gi = 0; gi < 32; gi += 4) {
        const float w0 = W[(size_t)(g0 + gi + 0) * H + h];
        const float w1 = W[(size_t)(g0 + gi + 1) * H + h];
        const float w2 = W[(size_t)(g0 + gi + 2) * H + h];
        const float w3 = W[(size_t)(g0 + gi + 3) * H + h];
#pragma unroll
        for (int b = 0; b < B; b++) {
            float4 hv = *reinterpret_cast<const float4*>(&sh[b][gi]);
            acc[b] = fmaf(hv.x, w0, acc[b]);
            acc[b] = fmaf(hv.y, w1, acc[b]);
            acc[b] = fmaf(hv.z, w2, acc[b]);
            acc[b] = fmaf(hv.w, w3, acc[b]);
        }
    }
#pragma unroll
    for (int b = 0; b < B; b++)
        g_vpart[blockIdx.y][b * H + h] = acc[b];
}

// ---------------------------------------------------------------------------
// Kernel 2: deterministic reduce of partials
// ---------------------------------------------------------------------------
__global__ void k_vreduce()
{
    const int i = blockIdx.x * blockDim.x + threadIdx.x;
    float s = 0.f;
#pragma unroll
    for (int gc = 0; gc < GCHUNKS; gc++) s += g_vpart[gc][i];
    g_v[i] = s;
}

// ---------------------------------------------------------------------------
// Kernel 3 (HBM-bound): energies[b,l] = v[b] . enc[l,b]
// Block = 256 threads = 8 warps, all sharing one b. v[b] (4 KB) is staged in
// shared memory ONCE per block -> the per-warp v reload (512 MB of L1/L2
// traffic in R1) becomes 64 MB total. Each warp handles one l:
// 8x LDG.128 (enc, coalesced) + 8x LDS.128 (v), butterfly reduce, 1 store.
// grid = (B, L/8).
// ---------------------------------------------------------------------------
__global__ void k_energies(const float* __restrict__ enc)
{
    __shared__ float4 sv[H / 4];             // 4 KB: v[b] as float4
    const int b = blockIdx.x;

    sv[threadIdx.x] = reinterpret_cast<const float4*>(g_v + (size_t)b * H)[threadIdx.x];
    __syncthreads();

    const int w    = threadIdx.x >> 5;
    const int lane = threadIdx.x & 31;
    const int l    = blockIdx.y * 8 + w;

    const float4* e4 = reinterpret_cast<const float4*>(enc + ((size_t)l * B + b) * H);

    float acc = 0.f;
#pragma unroll
    for (int i = 0; i < 8; i++) {
        float4 a = e4[lane + 32 * i];
        float4 v = sv[lane + 32 * i];
        acc = fmaf(a.x, v.x, acc);
        acc = fmaf(a.y, v.y, acc);
        acc = fmaf(a.z, v.z, acc);
        acc = fmaf(a.w, v.w, acc);
    }
#pragma unroll
    for (int off = 16; off; off >>= 1)
        acc += __shfl_xor_sync(0xFFFFFFFFu, acc, off);

    if (lane == 0) g_energies[(size_t)b * L + l] = acc;
}

// ---------------------------------------------------------------------------
// Kernel 4: row softmax over L, one block (1024 thr) per b. out[b,0,l].
// (hid.bias term is constant over l -> cancels in softmax -> omitted.)
// ---------------------------------------------------------------------------
__global__ void k_softmax(float* __restrict__ out)
{
    const int b   = blockIdx.x;
    const int tid = threadIdx.x;             // blockDim = 1024
    const float* e = &g_energies[(size_t)b * L];

    float vals[4];
    float m = -INFINITY;
#pragma unroll
    for (int i = 0; i < 4; i++) {
        vals[i] = e[tid + i * 1024];
        m = fmaxf(m, vals[i]);
    }

    __shared__ float red[32];
#pragma unroll
    for (int off = 16; off; off >>= 1)
        m = fmaxf(m, __shfl_xor_sync(0xFFFFFFFFu, m, off));
    if ((tid & 31) == 0) red[tid >> 5] = m;
    __syncthreads();
    if (tid < 32) {
        float t = red[tid];
#pragma unroll
        for (int off = 16; off; off >>= 1)
            t = fmaxf(t, __shfl_xor_sync(0xFFFFFFFFu, t, off));
        if (tid == 0) red[0] = t;
    }
    __syncthreads();
    m = red[0];
    __syncthreads();

    float s = 0.f;
#pragma unroll
    for (int i = 0; i < 4; i++) {
        vals[i] = __expf(vals[i] - m);
        s += vals[i];
    }
#pragma unroll
    for (int off = 16; off; off >>= 1)
        s += __shfl_xor_sync(0xFFFFFFFFu, s, off);
    if ((tid & 31) == 0) red[tid >> 5] = s;
    __syncthreads();
    if (tid < 32) {
        float t = red[tid];
#pragma unroll
        for (int off = 16; off; off >>= 1)
            t += __shfl_xor_sync(0xFFFFFFFFu, t, off);
        if (tid == 0) red[0] = t;
    }
    __syncthreads();
    const float inv = 1.f / red[0];

#pragma unroll
    for (int i = 0; i < 4; i++)
        out[(size_t)b * L + tid + i * 1024] = vals[i] * inv;
}

// ---------------------------------------------------------------------------
// Launch. Inputs (metadata order): hidden [1,B,H], encoder_outputs [L,B,H],
// W [H,H], b [H]. Output: [B,1,L] float32.
// ---------------------------------------------------------------------------
extern "C" void kernel_launch(void* const* d_in, const int* in_sizes, int n_in,
                              void* d_out, int out_size)
{
    const float* hid = (const float*)d_in[0];
    const float* enc = (const float*)d_in[1];
    const float* W   = (const float*)d_in[2];
    // d_in[3] (bias) cancels in softmax -> unused.
    float* out = (float*)d_out;

    k_vpart<<<dim3(H / 256, GCHUNKS), 256>>>(hid, W);
    k_vreduce<<<(B * H) / 256, 256>>>();
    k_energies<<<dim3(B, L / 8), 256>>>(enc);
    k_softmax<<<B, 1024>>>(out);
}